// round 16
// baseline (speedup 1.0000x reference)
#include <cuda_runtime.h>
#include <cuda_bf16.h>
#include <math.h>
#include <stdint.h>

#define BTN 16384
#define FN  32
#define HN  256
#define FHN 8192

// ---------------- scratch ----------------
__device__ __nv_bfloat16 g_cgh[(size_t)FN * HN * HN]; // w2@wg hi
__device__ __nv_bfloat16 g_cgl[(size_t)FN * HN * HN]; // w2@wg lo
__device__ __nv_bfloat16 g_cfh[(size_t)FN * HN * HN]; // w2@wf hi
__device__ __nv_bfloat16 g_cfl[(size_t)FN * HN * HN]; // w2@wf lo
__device__ __nv_bfloat16 g_s1h[(size_t)FHN * HN];     // sw1 hi
__device__ __nv_bfloat16 g_s1l[(size_t)FHN * HN];     // sw1 lo
__device__ float g_cbg[FN * HN];               // b2@wg + bg
__device__ float g_cbf[FN * HN];               // b2@wf + bf
__device__ float g_sg [(size_t)BTN * FN * HN]; // sigmoid(gate) [f][bt][h]
__device__ float g_stk[(size_t)BTN * FN * HN]; // [bt][f*H+h]
__device__ float g_sh [(size_t)BTN * HN];

__device__ __forceinline__ float eluf(float z) { return z > 0.f ? z : (__expf(z) - 1.f); }
__device__ __forceinline__ float sigf(float z) { return 1.f / (1.f + __expf(-z)); }

__device__ __forceinline__ uint32_t smem_u32(const void* p) {
    uint32_t a;
    asm("{ .reg .u64 t; cvta.to.shared.u64 t, %1; cvt.u32.u64 %0, t; }" : "=r"(a) : "l"(p));
    return a;
}
__device__ __forceinline__ void ldsm_x4(uint32_t* r, uint32_t a) {
    asm volatile("ldmatrix.sync.aligned.m8n8.x4.shared.b16 {%0,%1,%2,%3}, [%4];"
                 : "=r"(r[0]), "=r"(r[1]), "=r"(r[2]), "=r"(r[3]) : "r"(a));
}
__device__ __forceinline__ void ldsm_x4t(uint32_t* r, uint32_t a) {
    asm volatile("ldmatrix.sync.aligned.m8n8.x4.trans.shared.b16 {%0,%1,%2,%3}, [%4];"
                 : "=r"(r[0]), "=r"(r[1]), "=r"(r[2]), "=r"(r[3]) : "r"(a));
}
__device__ __forceinline__ void mmab(float* d, const uint32_t* a, uint32_t b0, uint32_t b1) {
    asm volatile("mma.sync.aligned.m16n8k16.row.col.f32.bf16.bf16.f32 "
                 "{%0,%1,%2,%3}, {%4,%5,%6,%7}, {%8,%9}, {%0,%1,%2,%3};"
                 : "+f"(d[0]), "+f"(d[1]), "+f"(d[2]), "+f"(d[3])
                 : "r"(a[0]), "r"(a[1]), "r"(a[2]), "r"(a[3]), "r"(b0), "r"(b1));
}
__device__ __forceinline__ uint32_t pack_hi2(float v0, float v1) {
    __nv_bfloat162 p = __floats2bfloat162_rn(v0, v1);
    return *(uint32_t*)&p;
}
__device__ __forceinline__ uint32_t pack_lo2(float v0, float v1) {
    float r0 = v0 - __bfloat162float(__float2bfloat16_rn(v0));
    float r1 = v1 - __bfloat162float(__float2bfloat16_rn(v1));
    __nv_bfloat162 p = __floats2bfloat162_rn(r0, r1);
    return *(uint32_t*)&p;
}

#define AST 80u
#define BST 528u
#define S_AL  10240
#define S_BH  20480
#define S_BL  37376
#define SM_1B 54272
// 2-CTA/SM shape (N=128)
#define BST2  272u
#define C_BH  20480u
#define C_BL  29184u
#define SM_2C 37888

// one 32-wide k-chunk: warp tile 32x64, acc[2][8][4], B row stride = bst
__device__ __forceinline__ void ktile(
    uint32_t aH, uint32_t aL, uint32_t bH, uint32_t bL, uint32_t bst,
    float (&acc)[2][8][4], int lane, int wm, int wn)
{
#pragma unroll
    for (int k16 = 0; k16 < 32; k16 += 16) {
        uint32_t Ah[2][4], Al[2][4];
#pragma unroll
        for (int mt = 0; mt < 2; mt++) {
            uint32_t ro = (uint32_t)(wm * 32 + mt * 16 + (lane & 15)) * AST
                        + (uint32_t)(k16 + ((lane >> 4) << 3)) * 2u;
            ldsm_x4(Ah[mt], aH + ro);
            ldsm_x4(Al[mt], aL + ro);
        }
        const int mat = lane >> 3;
#pragma unroll
        for (int nq = 0; nq < 4; nq++) {
            const int nb = wn * 64 + nq * 16;
            uint32_t bo = (uint32_t)(k16 + (mat & 1) * 8 + (lane & 7)) * bst
                        + (uint32_t)(nb + (mat >> 1) * 8) * 2u;
            uint32_t bh[4], bl[4];
            ldsm_x4t(bh, bH + bo);
            ldsm_x4t(bl, bL + bo);
#pragma unroll
            for (int mt = 0; mt < 2; mt++) {
                mmab(acc[mt][nq*2+0], Ah[mt], bh[0], bh[1]);
                mmab(acc[mt][nq*2+1], Ah[mt], bh[2], bh[3]);
                mmab(acc[mt][nq*2+0], Al[mt], bh[0], bh[1]);
                mmab(acc[mt][nq*2+1], Al[mt], bh[2], bh[3]);
                mmab(acc[mt][nq*2+0], Ah[mt], bl[0], bl[1]);
                mmab(acc[mt][nq*2+1], Ah[mt], bl[2], bl[3]);
            }
        }
    }
}

// ---------------------------------------------------------------------------
// k_wsplit (512 thr): C = w2[f] @ (z ? wf : wg)[f], OUTPUT split bf16 hi/lo.
// grid (2, FN, 2) — z selects gate/value weight product; fills 128 CTAs.
// ---------------------------------------------------------------------------
__global__ void __launch_bounds__(512, 1) k_wsplit(
    const float* __restrict__ A, const float* __restrict__ Bg, const float* __restrict__ Bf)
{
    extern __shared__ char sm[];
    const uint32_t smb = smem_u32(sm);
    const int tid = threadIdx.x, lane = tid & 31, wid = tid >> 5;
    const int wm = wid & 3, wn = wid >> 2;
    const int m0 = blockIdx.x * 128, f = blockIdx.y;
    const int z = blockIdx.z;
    const size_t WS = (size_t)HN * HN;
    const float* __restrict__ B = (z == 0) ? Bg : Bf;
    __nv_bfloat16* __restrict__ Chi = ((z == 0) ? g_cgh : g_cfh) + WS * f;
    __nv_bfloat16* __restrict__ Clo = ((z == 0) ? g_cgl : g_cfl) + WS * f;
    A += WS * f; B += WS * f;

    float acc[2][8][4];
#pragma unroll
    for (int a = 0; a < 2; a++)
#pragma unroll
        for (int b = 0; b < 8; b++)
#pragma unroll
            for (int c = 0; c < 4; c++) acc[a][b][c] = 0.f;

    float4 ra[2], rb[4];
#define LOAD_A(kt) do { \
    _Pragma("unroll") \
    for (int i = 0; i < 2; i++) { \
        const int u = tid + 512 * i; \
        const int row = u >> 3, cu = u & 7; \
        ra[i] = *(const float4*)(A + (size_t)(m0 + row) * HN + (kt) * 32 + cu * 4); \
    } } while (0)
#define LOAD_B(kt) do { \
    _Pragma("unroll") \
    for (int i = 0; i < 4; i++) { \
        const int u = tid + 512 * i; \
        const int row = u >> 6, cu = u & 63; \
        rb[i] = *(const float4*)(B + (size_t)((kt) * 32 + row) * HN + cu * 4); \
    } } while (0)
#define STAGE_AB() do { \
    _Pragma("unroll") \
    for (int i = 0; i < 2; i++) { \
        const int u = tid + 512 * i; \
        const int row = u >> 3, cu = u & 7; \
        const uint32_t o = row * AST + cu * 8; \
        *(uint2*)(sm + o)        = make_uint2(pack_hi2(ra[i].x, ra[i].y), pack_hi2(ra[i].z, ra[i].w)); \
        *(uint2*)(sm + S_AL + o) = make_uint2(pack_lo2(ra[i].x, ra[i].y), pack_lo2(ra[i].z, ra[i].w)); \
    } \
    _Pragma("unroll") \
    for (int i = 0; i < 4; i++) { \
        const int u = tid + 512 * i; \
        const int row = u >> 6, cu = u & 63; \
        const uint32_t o = row * BST + cu * 8; \
        *(uint2*)(sm + S_BH + o) = make_uint2(pack_hi2(rb[i].x, rb[i].y), pack_hi2(rb[i].z, rb[i].w)); \
        *(uint2*)(sm + S_BL + o) = make_uint2(pack_lo2(rb[i].x, rb[i].y), pack_lo2(rb[i].z, rb[i].w)); \
    } } while (0)

    LOAD_A(0); LOAD_B(0);
    for (int kt = 0; kt < 8; kt++) {
        STAGE_AB();
        __syncthreads();
        if (kt + 1 < 8) { LOAD_A(kt + 1); LOAD_B(kt + 1); }
        ktile(smb, smb + S_AL, smb + S_BH, smb + S_BL, BST, acc, lane, wm, wn);
        __syncthreads();
    }
#undef LOAD_A
#undef LOAD_B
#undef STAGE_AB

#pragma unroll
    for (int mt = 0; mt < 2; mt++)
#pragma unroll
        for (int j = 0; j < 8; j++) {
            const int n  = wn * 64 + j * 8 + (lane & 3) * 2;
            const int r0 = wm * 32 + mt * 16 + (lane >> 2);
            const size_t o0 = (size_t)(m0 + r0) * HN + n;
            const size_t o1 = (size_t)(m0 + r0 + 8) * HN + n;
            *(uint32_t*)(Chi + o0) = pack_hi2(acc[mt][j][0], acc[mt][j][1]);
            *(uint32_t*)(Clo + o0) = pack_lo2(acc[mt][j][0], acc[mt][j][1]);
            *(uint32_t*)(Chi + o1) = pack_hi2(acc[mt][j][2], acc[mt][j][3]);
            *(uint32_t*)(Clo + o1) = pack_lo2(acc[mt][j][2], acc[mt][j][3]);
        }
}

// ---------------------------------------------------------------------------
__global__ __launch_bounds__(256) void k_split(
    const float* __restrict__ src, __nv_bfloat16* __restrict__ hi, __nv_bfloat16* __restrict__ lo)
{
    const size_t i = ((size_t)blockIdx.x * 256 + threadIdx.x);
    float4 v = *(const float4*)(src + i * 4);
    *(uint2*)(hi + i * 4) = make_uint2(pack_hi2(v.x, v.y), pack_hi2(v.z, v.w));
    *(uint2*)(lo + i * 4) = make_uint2(pack_lo2(v.x, v.y), pack_lo2(v.z, v.w));
}

// ---------------------------------------------------------------------------
__global__ __launch_bounds__(256) void k_bias(
    const float* __restrict__ b2, const float* __restrict__ wg, const float* __restrict__ wf,
    const float* __restrict__ bg, const float* __restrict__ bf_)
{
    const int f = blockIdx.x, n = threadIdx.x;
    const float* W  = (blockIdx.y == 0) ? wg : wf;
    const float* bb = (blockIdx.y == 0) ? bg : bf_;
    float* out = (blockIdx.y == 0) ? g_cbg : g_cbf;
    float acc = bb[f * HN + n];
    const float* b2f_ = b2 + f * HN;
    const float* Wf_  = W + (size_t)f * HN * HN + n;
#pragma unroll 8
    for (int k = 0; k < HN; k++) acc += b2f_[k] * Wf_[(size_t)k * HN];
    out[f * HN + n] = acc;
}

// ---------------------------------------------------------------------------
// k_gate2: M=128, N=128 (grid.y = n-half), 256 thr, 2 CTAs/SM.
// ---------------------------------------------------------------------------
__global__ void __launch_bounds__(256, 2) k_gate2(
    const float* __restrict__ x, const float* __restrict__ w1, const float* __restrict__ b1)
{
    extern __shared__ char sm[];
    const uint32_t smb = smem_u32(sm);
    const int tid = threadIdx.x, lane = tid & 31, wid = tid >> 5;
    const int wm = wid & 3, wn = wid >> 2;
    const int m0 = blockIdx.x * 128;
    const int n0 = blockIdx.y * 128;
    const int f  = blockIdx.z;
    const size_t WS = (size_t)HN * HN;

    float acc[2][8][4];
#pragma unroll
    for (int a = 0; a < 2; a++)
#pragma unroll
        for (int b = 0; b < 8; b++)
#pragma unroll
            for (int c = 0; c < 4; c++) acc[a][b][c] = 0.f;

    const int grow = tid & 127, gseg = tid >> 7;
    const float xv = x[(m0 + grow) * FN + f];
    const float* __restrict__ w1f = w1 + f * HN;
    const float* __restrict__ b1f = b1 + f * HN;
    const __nv_bfloat16* __restrict__ Bh_ = g_cgh + WS * f + n0;
    const __nv_bfloat16* __restrict__ Bl_ = g_cgl + WS * f + n0;
    uint4 rbh[2], rbl[2];

#define G2_LOADB(kt) do { \
    _Pragma("unroll") \
    for (int i = 0; i < 2; i++) { \
        const int u = tid + 256 * i; \
        const int row = u >> 4, cu = u & 15; \
        rbh[i] = *(const uint4*)(Bh_ + (size_t)((kt) * 32 + row) * HN + cu * 8); \
        rbl[i] = *(const uint4*)(Bl_ + (size_t)((kt) * 32 + row) * HN + cu * 8); \
    } } while (0)
#define G2_STAGEB() do { \
    _Pragma("unroll") \
    for (int i = 0; i < 2; i++) { \
        const int u = tid + 256 * i; \
        const int row = u >> 4, cu = u & 15; \
        const uint32_t o = row * BST2 + cu * 16; \
        *(uint4*)(sm + C_BH + o) = rbh[i]; \
        *(uint4*)(sm + C_BL + o) = rbl[i]; \
    } } while (0)
#define G2_GENA(k0) do { \
    _Pragma("unroll") \
    for (int oct = 0; oct < 2; oct++) { \
        const int kk = (k0) + gseg * 16 + oct * 8; \
        float4 wa = *(const float4*)(w1f + kk),  wb = *(const float4*)(w1f + kk + 4); \
        float4 ca = *(const float4*)(b1f + kk),  cb = *(const float4*)(b1f + kk + 4); \
        float v[8] = { eluf(xv*wa.x+ca.x), eluf(xv*wa.y+ca.y), eluf(xv*wa.z+ca.z), eluf(xv*wa.w+ca.w), \
                       eluf(xv*wb.x+cb.x), eluf(xv*wb.y+cb.y), eluf(xv*wb.z+cb.z), eluf(xv*wb.w+cb.w) }; \
        uint4 H = { pack_hi2(v[0],v[1]), pack_hi2(v[2],v[3]), pack_hi2(v[4],v[5]), pack_hi2(v[6],v[7]) }; \
        uint4 L = { pack_lo2(v[0],v[1]), pack_lo2(v[2],v[3]), pack_lo2(v[4],v[5]), pack_lo2(v[6],v[7]) }; \
        const uint32_t o = grow * AST + gseg * 32 + oct * 16; \
        *(uint4*)(sm + o) = H; \
        *(uint4*)(sm + S_AL + o) = L; \
    } } while (0)

    G2_LOADB(0);
    for (int kt = 0; kt < 8; kt++) {
        G2_GENA(kt * 32);
        G2_STAGEB();
        __syncthreads();
        if (kt + 1 < 8) G2_LOADB(kt + 1);
        ktile(smb, smb + S_AL, smb + C_BH, smb + C_BL, BST2, acc, lane, wm, wn);
        __syncthreads();
    }
#undef G2_LOADB
#undef G2_STAGEB
#undef G2_GENA

#pragma unroll
    for (int mt = 0; mt < 2; mt++)
#pragma unroll
        for (int j = 0; j < 8; j++) {
            const int n  = n0 + wn * 64 + j * 8 + (lane & 3) * 2;
            const int r0 = wm * 32 + mt * 16 + (lane >> 2);
            float2 bb = *(const float2*)(g_cbg + f * HN + n);
            float2 o0 = { sigf(acc[mt][j][0] + bb.x), sigf(acc[mt][j][1] + bb.y) };
            float2 o1 = { sigf(acc[mt][j][2] + bb.x), sigf(acc[mt][j][3] + bb.y) };
            *(float2*)(g_sg + ((size_t)f * BTN + m0 + r0) * HN + n) = o0;
            *(float2*)(g_sg + ((size_t)f * BTN + m0 + r0 + 8) * HN + n) = o1;
        }
}

// ---------------------------------------------------------------------------
// k_val: value GEMM + GLU + skip + LN fused (512 thr, M=128/N=256).
// ---------------------------------------------------------------------------
__global__ void __launch_bounds__(512, 1) k_val(
    const float* __restrict__ x, const float* __restrict__ w1, const float* __restrict__ b1,
    const float* __restrict__ ws, const float* __restrict__ bs,
    const float* __restrict__ gamma, const float* __restrict__ beta)
{
    extern __shared__ char sm[];
    const uint32_t smb = smem_u32(sm);
    const int tid = threadIdx.x, lane = tid & 31, wid = tid >> 5;
    const int wm = wid & 3, wn = wid >> 2;
    const int m0 = blockIdx.x * 128, f = blockIdx.y;

    float acc[2][8][4];
#pragma unroll
    for (int a = 0; a < 2; a++)
#pragma unroll
        for (int b = 0; b < 8; b++)
#pragma unroll
            for (int c = 0; c < 4; c++) acc[a][b][c] = 0.f;

    const int grow = tid & 127, gseg = tid >> 7;
    const float xv = x[(m0 + grow) * FN + f];
    const float* __restrict__ w1f = w1 + f * HN;
    const float* __restrict__ b1f = b1 + f * HN;
    const __nv_bfloat16* __restrict__ Bh_ = g_cfh + (size_t)f * HN * HN;
    const __nv_bfloat16* __restrict__ Bl_ = g_cfl + (size_t)f * HN * HN;
    uint4 rbh[2], rbl[2];

#define V_GENA(k0) do { \
    const int kk = (k0) + gseg * 8; \
    float4 wa = *(const float4*)(w1f + kk),  wb = *(const float4*)(w1f + kk + 4); \
    float4 ca = *(const float4*)(b1f + kk),  cb = *(const float4*)(b1f + kk + 4); \
    float v[8] = { eluf(xv*wa.x+ca.x), eluf(xv*wa.y+ca.y), eluf(xv*wa.z+ca.z), eluf(xv*wa.w+ca.w), \
                   eluf(xv*wb.x+cb.x), eluf(xv*wb.y+cb.y), eluf(xv*wb.z+cb.z), eluf(xv*wb.w+cb.w) }; \
    uint4 H = { pack_hi2(v[0],v[1]), pack_hi2(v[2],v[3]), pack_hi2(v[4],v[5]), pack_hi2(v[6],v[7]) }; \
    uint4 L = { pack_lo2(v[0],v[1]), pack_lo2(v[2],v[3]), pack_lo2(v[4],v[5]), pack_lo2(v[6],v[7]) }; \
    const uint32_t o = grow * AST + gseg * 16; \
    *(uint4*)(sm + o) = H; \
    *(uint4*)(sm + S_AL + o) = L; } while (0)
#define V_LOADB(kt) do { \
    _Pragma("unroll") \
    for (int i = 0; i < 2; i++) { \
        const int u = tid + 512 * i; \
        const int row = u >> 5, cu = u & 31; \
        rbh[i] = *(const uint4*)(Bh_ + (size_t)((kt) * 32 + row) * HN + cu * 8); \
        rbl[i] = *(const uint4*)(Bl_ + (size_t)((kt) * 32 + row) * HN + cu * 8); \
    } } while (0)
#define V_STAGEB() do { \
    _Pragma("unroll") \
    for (int i = 0; i < 2; i++) { \
        const int u = tid + 512 * i; \
        const int row = u >> 5, cu = u & 31; \
        const uint32_t o = row * BST + cu * 16; \
        *(uint4*)(sm + S_BH + o) = rbh[i]; \
        *(uint4*)(sm + S_BL + o) = rbl[i]; \
    } } while (0)

    V_LOADB(0);
    for (int kt = 0; kt < 8; kt++) {
        V_GENA(kt * 32);
        V_STAGEB();
        __syncthreads();
        if (kt + 1 < 8) V_LOADB(kt + 1);
        ktile(smb, smb + S_AL, smb + S_BH, smb + S_BL, BST, acc, lane, wm, wn);
        __syncthreads();
    }
#undef V_GENA
#undef V_LOADB
#undef V_STAGEB

    // --- epilogue: GLU + skip into acc (in place) ---
#pragma unroll
    for (int mt = 0; mt < 2; mt++) {
        const int rA = m0 + wm * 32 + mt * 16 + (lane >> 2);
        const float xa = x[rA * FN + f];
        const float xb = x[(rA + 8) * FN + f];
#pragma unroll
        for (int j = 0; j < 8; j++) {
            const int n = wn * 64 + j * 8 + (lane & 3) * 2;
            float2 cb  = *(const float2*)(g_cbf + f * HN + n);
            float2 wsv = *(const float2*)(ws + f * HN + n);
            float2 bsv = *(const float2*)(bs + f * HN + n);
            float2 sg0 = *(const float2*)(g_sg + ((size_t)f * BTN + rA) * HN + n);
            float2 sg1 = *(const float2*)(g_sg + ((size_t)f * BTN + rA + 8) * HN + n);
            acc[mt][j][0] = sg0.x * (acc[mt][j][0] + cb.x) + xa * wsv.x + bsv.x;
            acc[mt][j][1] = sg0.y * (acc[mt][j][1] + cb.y) + xa * wsv.y + bsv.y;
            acc[mt][j][2] = sg1.x * (acc[mt][j][2] + cb.x) + xb * wsv.x + bsv.x;
            acc[mt][j][3] = sg1.y * (acc[mt][j][3] + cb.y) + xb * wsv.y + bsv.y;
        }
    }
    // --- LN partials ---
    float2* part = (float2*)sm;   // [128 rows][4 wn]
#pragma unroll
    for (int mt = 0; mt < 2; mt++) {
        float s0 = 0.f, q0 = 0.f, s1 = 0.f, q1 = 0.f;
#pragma unroll
        for (int j = 0; j < 8; j++) {
            s0 += acc[mt][j][0] + acc[mt][j][1];
            q0 += acc[mt][j][0] * acc[mt][j][0] + acc[mt][j][1] * acc[mt][j][1];
            s1 += acc[mt][j][2] + acc[mt][j][3];
            q1 += acc[mt][j][2] * acc[mt][j][2] + acc[mt][j][3] * acc[mt][j][3];
        }
#pragma unroll
        for (int o = 1; o <= 2; o <<= 1) {
            s0 += __shfl_xor_sync(0xffffffffu, s0, o);
            q0 += __shfl_xor_sync(0xffffffffu, q0, o);
            s1 += __shfl_xor_sync(0xffffffffu, s1, o);
            q1 += __shfl_xor_sync(0xffffffffu, q1, o);
        }
        if ((lane & 3) == 0) {
            const int r0 = wm * 32 + mt * 16 + (lane >> 2);
            part[r0 * 4 + wn]       = make_float2(s0, q0);
            part[(r0 + 8) * 4 + wn] = make_float2(s1, q1);
        }
    }
    __syncthreads();
#pragma unroll
    for (int mt = 0; mt < 2; mt++) {
        const int r0 = wm * 32 + mt * 16 + (lane >> 2);
        float2 p0 = part[r0 * 4 + 0], p1 = part[r0 * 4 + 1];
        float2 p2 = part[r0 * 4 + 2], p3 = part[r0 * 4 + 3];
        float sA = p0.x + p1.x + p2.x + p3.x, qA = p0.y + p1.y + p2.y + p3.y;
        p0 = part[(r0 + 8) * 4 + 0]; p1 = part[(r0 + 8) * 4 + 1];
        p2 = part[(r0 + 8) * 4 + 2]; p3 = part[(r0 + 8) * 4 + 3];
        float sB = p0.x + p1.x + p2.x + p3.x, qB = p0.y + p1.y + p2.y + p3.y;
        const float mA = sA * (1.f / 256.f);
        float vA = qA * (1.f / 256.f) - mA * mA; vA = vA > 0.f ? vA : 0.f;
        const float rA_ = rsqrtf(vA + 1e-5f);
        const float mB = sB * (1.f / 256.f);
        float vB = qB * (1.f / 256.f) - mB * mB; vB = vB > 0.f ? vB : 0.f;
        const float rB_ = rsqrtf(vB + 1e-5f);
        float* o0p = g_stk + (size_t)(m0 + r0) * FHN + f * HN;
        float* o1p = g_stk + (size_t)(m0 + r0 + 8) * FHN + f * HN;
#pragma unroll
        for (int j = 0; j < 8; j++) {
            const int n = wn * 64 + j * 8 + (lane & 3) * 2;
            float2 gm = *(const float2*)(gamma + f * HN + n);
            float2 bt = *(const float2*)(beta + f * HN + n);
            *(float2*)(o0p + n) = make_float2((acc[mt][j][0] - mA) * rA_ * gm.x + bt.x,
                                              (acc[mt][j][1] - mA) * rA_ * gm.y + bt.y);
            *(float2*)(o1p + n) = make_float2((acc[mt][j][2] - mB) * rB_ * gm.x + bt.x,
                                              (acc[mt][j][3] - mB) * rB_ * gm.y + bt.y);
        }
    }
}

// ---------------------------------------------------------------------------
// k_gemmS2: M=128, N=128, 256 thr, 2 CTAs/SM. A fp32 converted at stage time.
// ---------------------------------------------------------------------------
__global__ void __launch_bounds__(256, 2) k_gemmS2(const float* __restrict__ sb1)
{
    extern __shared__ char sm[];
    const uint32_t smb = smem_u32(sm);
    const int tid = threadIdx.x, lane = tid & 31, wid = tid >> 5;
    const int wm = wid & 3, wn = wid >> 2;
    const int m0 = blockIdx.x * 128;
    const int n0 = blockIdx.y * 128;

    float acc[2][8][4];
#pragma unroll
    for (int a = 0; a < 2; a++)
#pragma unroll
        for (int b = 0; b < 8; b++)
#pragma unroll
            for (int c = 0; c < 4; c++) acc[a][b][c] = 0.f;

    const __nv_bfloat16* __restrict__ Bh_ = g_s1h + n0;
    const __nv_bfloat16* __restrict__ Bl_ = g_s1l + n0;
    uint4 rbh[2], rbl[2];

#define S2_LOADB(kt) do { \
    _Pragma("unroll") \
    for (int i = 0; i < 2; i++) { \
        const int u = tid + 256 * i; \
        const int row = u >> 4, cu = u & 15; \
        rbh[i] = *(const uint4*)(Bh_ + (size_t)((kt) * 32 + row) * HN + cu * 8); \
        rbl[i] = *(const uint4*)(Bl_ + (size_t)((kt) * 32 + row) * HN + cu * 8); \
    } } while (0)
#define S2_STAGEB() do { \
    _Pragma("unroll") \
    for (int i = 0; i < 2; i++) { \
        const int u = tid + 256 * i; \
        const int row = u >> 4, cu = u & 15; \
        const uint32_t o = row * BST2 + cu * 16; \
        *(uint4*)(sm + C_BH + o) = rbh[i]; \
        *(uint4*)(sm + C_BL + o) = rbl[i]; \
    } } while (0)
#define S2_STAGEA(kt) do { \
    _Pragma("unroll") \
    for (int i = 0; i < 4; i++) { \
        const int u = tid + 256 * i; \
        const int row = u >> 3, cu = u & 7; \
        float4 v = *(const float4*)(g_stk + (size_t)(m0 + row) * FHN + (kt) * 32 + cu * 4); \
        const uint32_t o = row * AST + cu * 8; \
        *(uint2*)(sm + o)        = make_uint2(pack_hi2(v.x, v.y), pack_hi2(v.z, v.w)); \
        *(uint2*)(sm + S_AL + o) = make_uint2(pack_lo2(v.x, v.y), pack_lo2(v.z, v.w)); \
    } } while (0)

    S2_LOADB(0);
    const int C = FHN / 32;
    for (int kt = 0; kt < C; kt++) {
        S2_STAGEA(kt);
        S2_STAGEB();
        __syncthreads();
        if (kt + 1 < C) S2_LOADB(kt + 1);
        ktile(smb, smb + S_AL, smb + C_BH, smb + C_BL, BST2, acc, lane, wm, wn);
        __syncthreads();
    }
#undef S2_LOADB
#undef S2_STAGEB
#undef S2_STAGEA

#pragma unroll
    for (int mt = 0; mt < 2; mt++)
#pragma unroll
        for (int j = 0; j < 8; j++) {
            const int n  = n0 + wn * 64 + j * 8 + (lane & 3) * 2;
            const int r0 = wm * 32 + mt * 16 + (lane >> 2);
            float2 bb = *(const float2*)(sb1 + n);
            float2 o0 = { eluf(acc[mt][j][0] + bb.x), eluf(acc[mt][j][1] + bb.y) };
            float2 o1 = { eluf(acc[mt][j][2] + bb.x), eluf(acc[mt][j][3] + bb.y) };
            *(float2*)(g_sh + (size_t)(m0 + r0) * HN + n) = o0;
            *(float2*)(g_sh + (size_t)(m0 + r0 + 8) * HN + n) = o1;
        }
}

// ---------------------------------------------------------------------------
// k_tail2: fused sres + selection + weighted output sum (fp32 stk).
// One warp per token. Phase C re-reads the same stk rows as phase A -> L2 hit.
// Accumulation orders identical to the previous k_selt/k_out (bitwise-same).
// ---------------------------------------------------------------------------
__global__ __launch_bounds__(256) void k_tail2(
    const float* __restrict__ ssw, const float* __restrict__ ssb,
    const float* __restrict__ sw2, const float* __restrict__ sb2,
    const float* __restrict__ swg, const float* __restrict__ sbg,
    const float* __restrict__ swf, const float* __restrict__ sbf,
    const float* __restrict__ sgm, const float* __restrict__ sbt,
    float* __restrict__ out)
{
    const int lane = threadIdx.x & 31;
    const int m    = blockIdx.x * 8 + (threadIdx.x >> 5);
    const float* __restrict__ a = g_stk + (size_t)m * FHN;

    // --- phase A: sres[lane] ---
    float sres = 0.f;
#pragma unroll 4
    for (int k = 0; k < FHN; k += 4) {
        float4 av = *(const float4*)(a + k);
        sres += av.x * ssw[(k + 0) * FN + lane];
        sres += av.y * ssw[(k + 1) * FN + lane];
        sres += av.z * ssw[(k + 2) * FN + lane];
        sres += av.w * ssw[(k + 3) * FN + lane];
    }
    sres += ssb[lane];

    // --- phase B: selection (lane = feature) ---
    const float* __restrict__ sh = g_sh + (size_t)m * HN;
    float shv[8];
#pragma unroll
    for (int i = 0; i < 8; i++) shv[i] = sh[i * 32 + lane];
    float acc = sb2[lane];
#pragma unroll 8
    for (int h = 0; h < HN; h++) {
        float s = __shfl_sync(0xffffffffu, shv[h >> 5], h & 31);
        acc += s * sw2[h * FN + lane];
    }
    float ag = sbg[lane], af = sbf[lane];
#pragma unroll
    for (int i = 0; i < FN; i++) {
        float s = __shfl_sync(0xffffffffu, acc, i);
        ag += s * swg[i * FN + lane];
        af += s * swf[i * FN + lane];
    }
    const float pre = sres + sigf(ag) * af;
    float s1 = pre;
#pragma unroll
    for (int o = 16; o > 0; o >>= 1) s1 += __shfl_xor_sync(0xffffffffu, s1, o);
    const float mean = s1 * (1.f / 32.f);
    const float d = pre - mean;
    float q = d * d;
#pragma unroll
    for (int o = 16; o > 0; o >>= 1) q += __shfl_xor_sync(0xffffffffu, q, o);
    const float y = d * rsqrtf(q * (1.f / 32.f) + 1e-5f) * sgm[lane] + sbt[lane];
    float mx = y;
#pragma unroll
    for (int o = 16; o > 0; o >>= 1) mx = fmaxf(mx, __shfl_xor_sync(0xffffffffu, mx, o));
    const float e = __expf(y - mx);
    float se = e;
#pragma unroll
    for (int o = 16; o > 0; o >>= 1) se += __shfl_xor_sync(0xffffffffu, se, o);
    const float wtv = e / se;   // softmax weight for feature 'lane'

    // --- phase C: out[m][h] = sum_f stk[m][f*HN+h] * wts[f]  (lane = h-octet) ---
    const int h0 = lane * 8;
    float o0 = 0.f, o1 = 0.f, o2 = 0.f, o3 = 0.f;
    float o4 = 0.f, o5 = 0.f, o6 = 0.f, o7 = 0.f;
#pragma unroll 4
    for (int f = 0; f < FN; f++) {
        const float wv = __shfl_sync(0xffffffffu, wtv, f);
        float4 va = *(const float4*)(a + f * HN + h0);
        float4 vb = *(const float4*)(a + f * HN + h0 + 4);
        o0 += wv * va.x; o1 += wv * va.y; o2 += wv * va.z; o3 += wv * va.w;
        o4 += wv * vb.x; o5 += wv * vb.y; o6 += wv * vb.z; o7 += wv * vb.w;
    }
    *(float4*)(out + (size_t)m * HN + h0)     = make_float4(o0, o1, o2, o3);
    *(float4*)(out + (size_t)m * HN + h0 + 4) = make_float4(o4, o5, o6, o7);
}

// ---------------------------------------------------------------------------
extern "C" void kernel_launch(void* const* d_in, const int* in_sizes, int n_in,
                              void* d_out, int out_size)
{
    const float* x    = (const float*)d_in[0];
    const float* w1   = (const float*)d_in[1];
    const float* b1   = (const float*)d_in[2];
    const float* w2   = (const float*)d_in[3];
    const float* b2   = (const float*)d_in[4];
    const float* wg   = (const float*)d_in[5];
    const float* bg   = (const float*)d_in[6];
    const float* wf   = (const float*)d_in[7];
    const float* bf   = (const float*)d_in[8];
    const float* gamma= (const float*)d_in[9];
    const float* beta = (const float*)d_in[10];
    const float* ws   = (const float*)d_in[11];
    const float* bs   = (const float*)d_in[12];
    const float* sw1  = (const float*)d_in[13];
    const float* sb1  = (const float*)d_in[14];
    const float* sw2  = (const float*)d_in[15];
    const float* sb2  = (const float*)d_in[16];
    const float* swg  = (const float*)d_in[17];
    const float* sbg  = (const float*)d_in[18];
    const float* swf  = (const float*)d_in[19];
    const float* sbf  = (const float*)d_in[20];
    const float* sgm  = (const float*)d_in[21];
    const float* sbt  = (const float*)d_in[22];
    const float* ssw  = (const float*)d_in[23];
    const float* ssb  = (const float*)d_in[24];
    float* out = (float*)d_out;

    cudaFuncSetAttribute(k_wsplit, cudaFuncAttributeMaxDynamicSharedMemorySize, SM_1B);
    cudaFuncSetAttribute(k_gate2,  cudaFuncAttributeMaxDynamicSharedMemorySize, SM_2C);
    cudaFuncSetAttribute(k_val,    cudaFuncAttributeMaxDynamicSharedMemorySize, SM_1B);
    cudaFuncSetAttribute(k_gemmS2, cudaFuncAttributeMaxDynamicSharedMemorySize, SM_2C);

    __nv_bfloat16 *s1h, *s1l;
    cudaGetSymbolAddress((void**)&s1h, g_s1h);
    cudaGetSymbolAddress((void**)&s1l, g_s1l);

    // prep: both weight-products in one launch (fills 128 CTAs), sw1 split, biases
    k_wsplit<<<dim3(2, FN, 2), 512, SM_1B>>>(w2, wg, wf);
    k_bias  <<<dim3(FN, 2), 256>>>(b2, wg, wf, bg, bf);
    k_split <<<(FHN * HN) / 1024, 256>>>(sw1, s1h, s1l);

    k_gate2<<<dim3(BTN / 128, 2, FN), 256, SM_2C>>>(x, w1, b1);
    k_val  <<<dim3(BTN / 128, FN), 512, SM_1B>>>(x, w1, b1, ws, bs, gamma, beta);

    k_gemmS2<<<dim3(BTN / 128, 2), 256, SM_2C>>>(sb1);
    k_tail2 <<<BTN / 8, 256>>>(ssw, ssb, sw2, sb2, swg, sbg, swf, sbf, sgm, sbt, out);
}

// round 17
// speedup vs baseline: 1.1089x; 1.1089x over previous
#include <cuda_runtime.h>
#include <cuda_bf16.h>
#include <math.h>
#include <stdint.h>

#define BTN 16384
#define FN  32
#define HN  256
#define FHN 8192

// ---------------- scratch ----------------
__device__ __nv_bfloat16 g_cgh[(size_t)FN * HN * HN]; // w2@wg hi
__device__ __nv_bfloat16 g_cgl[(size_t)FN * HN * HN]; // w2@wg lo
__device__ __nv_bfloat16 g_cfh[(size_t)FN * HN * HN]; // w2@wf hi
__device__ __nv_bfloat16 g_cfl[(size_t)FN * HN * HN]; // w2@wf lo
__device__ __nv_bfloat16 g_s1h[(size_t)FHN * HN];     // sw1 hi
__device__ __nv_bfloat16 g_s1l[(size_t)FHN * HN];     // sw1 lo
__device__ float g_cbg[FN * HN];               // b2@wg + bg
__device__ float g_cbf[FN * HN];               // b2@wf + bf
__device__ float g_sg [(size_t)BTN * FN * HN]; // sigmoid(gate) [f][bt][h]
__device__ float g_stk[(size_t)BTN * FN * HN]; // [bt][f*H+h]
__device__ float g_sh [(size_t)BTN * HN];
__device__ float g_wts [BTN * FN];

__device__ __forceinline__ float eluf(float z) { return z > 0.f ? z : (__expf(z) - 1.f); }
__device__ __forceinline__ float sigf(float z) { return 1.f / (1.f + __expf(-z)); }

__device__ __forceinline__ uint32_t smem_u32(const void* p) {
    uint32_t a;
    asm("{ .reg .u64 t; cvta.to.shared.u64 t, %1; cvt.u32.u64 %0, t; }" : "=r"(a) : "l"(p));
    return a;
}
__device__ __forceinline__ void ldsm_x4(uint32_t* r, uint32_t a) {
    asm volatile("ldmatrix.sync.aligned.m8n8.x4.shared.b16 {%0,%1,%2,%3}, [%4];"
                 : "=r"(r[0]), "=r"(r[1]), "=r"(r[2]), "=r"(r[3]) : "r"(a));
}
__device__ __forceinline__ void ldsm_x4t(uint32_t* r, uint32_t a) {
    asm volatile("ldmatrix.sync.aligned.m8n8.x4.trans.shared.b16 {%0,%1,%2,%3}, [%4];"
                 : "=r"(r[0]), "=r"(r[1]), "=r"(r[2]), "=r"(r[3]) : "r"(a));
}
__device__ __forceinline__ void mmab(float* d, const uint32_t* a, uint32_t b0, uint32_t b1) {
    asm volatile("mma.sync.aligned.m16n8k16.row.col.f32.bf16.bf16.f32 "
                 "{%0,%1,%2,%3}, {%4,%5,%6,%7}, {%8,%9}, {%0,%1,%2,%3};"
                 : "+f"(d[0]), "+f"(d[1]), "+f"(d[2]), "+f"(d[3])
                 : "r"(a[0]), "r"(a[1]), "r"(a[2]), "r"(a[3]), "r"(b0), "r"(b1));
}
__device__ __forceinline__ uint32_t pack_hi2(float v0, float v1) {
    __nv_bfloat162 p = __floats2bfloat162_rn(v0, v1);
    return *(uint32_t*)&p;
}
__device__ __forceinline__ uint32_t pack_lo2(float v0, float v1) {
    float r0 = v0 - __bfloat162float(__float2bfloat16_rn(v0));
    float r1 = v1 - __bfloat162float(__float2bfloat16_rn(v1));
    __nv_bfloat162 p = __floats2bfloat162_rn(r0, r1);
    return *(uint32_t*)&p;
}

#define AST 80u
#define BST 528u
#define S_AL  10240
#define S_BH  20480
#define S_BL  37376
#define SM_1B 54272
// 2-CTA/SM shape (N=128)
#define BST2  272u
#define C_BH  20480u
#define C_BL  29184u
#define SM_2C 37888

// one 32-wide k-chunk: warp tile 32x64, acc[2][8][4], B row stride = bst
__device__ __forceinline__ void ktile(
    uint32_t aH, uint32_t aL, uint32_t bH, uint32_t bL, uint32_t bst,
    float (&acc)[2][8][4], int lane, int wm, int wn)
{
#pragma unroll
    for (int k16 = 0; k16 < 32; k16 += 16) {
        uint32_t Ah[2][4], Al[2][4];
#pragma unroll
        for (int mt = 0; mt < 2; mt++) {
            uint32_t ro = (uint32_t)(wm * 32 + mt * 16 + (lane & 15)) * AST
                        + (uint32_t)(k16 + ((lane >> 4) << 3)) * 2u;
            ldsm_x4(Ah[mt], aH + ro);
            ldsm_x4(Al[mt], aL + ro);
        }
        const int mat = lane >> 3;
#pragma unroll
        for (int nq = 0; nq < 4; nq++) {
            const int nb = wn * 64 + nq * 16;
            uint32_t bo = (uint32_t)(k16 + (mat & 1) * 8 + (lane & 7)) * bst
                        + (uint32_t)(nb + (mat >> 1) * 8) * 2u;
            uint32_t bh[4], bl[4];
            ldsm_x4t(bh, bH + bo);
            ldsm_x4t(bl, bL + bo);
#pragma unroll
            for (int mt = 0; mt < 2; mt++) {
                mmab(acc[mt][nq*2+0], Ah[mt], bh[0], bh[1]);
                mmab(acc[mt][nq*2+1], Ah[mt], bh[2], bh[3]);
                mmab(acc[mt][nq*2+0], Al[mt], bh[0], bh[1]);
                mmab(acc[mt][nq*2+1], Al[mt], bh[2], bh[3]);
                mmab(acc[mt][nq*2+0], Ah[mt], bl[0], bl[1]);
                mmab(acc[mt][nq*2+1], Ah[mt], bl[2], bl[3]);
            }
        }
    }
}

// ---------------------------------------------------------------------------
// k_wsplit (512 thr): C = A[f] @ B[f] (fp32 in), OUTPUT split bf16 hi/lo.
// ---------------------------------------------------------------------------
__global__ void __launch_bounds__(512, 1) k_wsplit(
    const float* __restrict__ A, const float* __restrict__ B,
    __nv_bfloat16* __restrict__ Chi, __nv_bfloat16* __restrict__ Clo)
{
    extern __shared__ char sm[];
    const uint32_t smb = smem_u32(sm);
    const int tid = threadIdx.x, lane = tid & 31, wid = tid >> 5;
    const int wm = wid & 3, wn = wid >> 2;
    const int m0 = blockIdx.x * 128, f = blockIdx.y;
    const size_t WS = (size_t)HN * HN;
    A += WS * f; B += WS * f; Chi += WS * f; Clo += WS * f;

    float acc[2][8][4];
#pragma unroll
    for (int a = 0; a < 2; a++)
#pragma unroll
        for (int b = 0; b < 8; b++)
#pragma unroll
            for (int c = 0; c < 4; c++) acc[a][b][c] = 0.f;

    float4 ra[2], rb[4];
#define LOAD_A(kt) do { \
    _Pragma("unroll") \
    for (int i = 0; i < 2; i++) { \
        const int u = tid + 512 * i; \
        const int row = u >> 3, cu = u & 7; \
        ra[i] = *(const float4*)(A + (size_t)(m0 + row) * HN + (kt) * 32 + cu * 4); \
    } } while (0)
#define LOAD_B(kt) do { \
    _Pragma("unroll") \
    for (int i = 0; i < 4; i++) { \
        const int u = tid + 512 * i; \
        const int row = u >> 6, cu = u & 63; \
        rb[i] = *(const float4*)(B + (size_t)((kt) * 32 + row) * HN + cu * 4); \
    } } while (0)
#define STAGE_AB() do { \
    _Pragma("unroll") \
    for (int i = 0; i < 2; i++) { \
        const int u = tid + 512 * i; \
        const int row = u >> 3, cu = u & 7; \
        const uint32_t o = row * AST + cu * 8; \
        *(uint2*)(sm + o)        = make_uint2(pack_hi2(ra[i].x, ra[i].y), pack_hi2(ra[i].z, ra[i].w)); \
        *(uint2*)(sm + S_AL + o) = make_uint2(pack_lo2(ra[i].x, ra[i].y), pack_lo2(ra[i].z, ra[i].w)); \
    } \
    _Pragma("unroll") \
    for (int i = 0; i < 4; i++) { \
        const int u = tid + 512 * i; \
        const int row = u >> 6, cu = u & 63; \
        const uint32_t o = row * BST + cu * 8; \
        *(uint2*)(sm + S_BH + o) = make_uint2(pack_hi2(rb[i].x, rb[i].y), pack_hi2(rb[i].z, rb[i].w)); \
        *(uint2*)(sm + S_BL + o) = make_uint2(pack_lo2(rb[i].x, rb[i].y), pack_lo2(rb[i].z, rb[i].w)); \
    } } while (0)

    LOAD_A(0); LOAD_B(0);
    for (int kt = 0; kt < 8; kt++) {
        STAGE_AB();
        __syncthreads();
        if (kt + 1 < 8) { LOAD_A(kt + 1); LOAD_B(kt + 1); }
        ktile(smb, smb + S_AL, smb + S_BH, smb + S_BL, BST, acc, lane, wm, wn);
        __syncthreads();
    }
#undef LOAD_A
#undef LOAD_B
#undef STAGE_AB

#pragma unroll
    for (int mt = 0; mt < 2; mt++)
#pragma unroll
        for (int j = 0; j < 8; j++) {
            const int n  = wn * 64 + j * 8 + (lane & 3) * 2;
            const int r0 = wm * 32 + mt * 16 + (lane >> 2);
            const size_t o0 = (size_t)(m0 + r0) * HN + n;
            const size_t o1 = (size_t)(m0 + r0 + 8) * HN + n;
            *(uint32_t*)(Chi + o0) = pack_hi2(acc[mt][j][0], acc[mt][j][1]);
            *(uint32_t*)(Clo + o0) = pack_lo2(acc[mt][j][0], acc[mt][j][1]);
            *(uint32_t*)(Chi + o1) = pack_hi2(acc[mt][j][2], acc[mt][j][3]);
            *(uint32_t*)(Clo + o1) = pack_lo2(acc[mt][j][2], acc[mt][j][3]);
        }
}

// ---------------------------------------------------------------------------
__global__ __launch_bounds__(256) void k_split(
    const float* __restrict__ src, __nv_bfloat16* __restrict__ hi, __nv_bfloat16* __restrict__ lo)
{
    const size_t i = ((size_t)blockIdx.x * 256 + threadIdx.x);
    float4 v = *(const float4*)(src + i * 4);
    *(uint2*)(hi + i * 4) = make_uint2(pack_hi2(v.x, v.y), pack_hi2(v.z, v.w));
    *(uint2*)(lo + i * 4) = make_uint2(pack_lo2(v.x, v.y), pack_lo2(v.z, v.w));
}

// ---------------------------------------------------------------------------
__global__ __launch_bounds__(256) void k_bias(
    const float* __restrict__ b2, const float* __restrict__ wg, const float* __restrict__ wf,
    const float* __restrict__ bg, const float* __restrict__ bf_)
{
    const int f = blockIdx.x, n = threadIdx.x;
    const float* W  = (blockIdx.y == 0) ? wg : wf;
    const float* bb = (blockIdx.y == 0) ? bg : bf_;
    float* out = (blockIdx.y == 0) ? g_cbg : g_cbf;
    float acc = bb[f * HN + n];
    const float* b2f_ = b2 + f * HN;
    const float* Wf_  = W + (size_t)f * HN * HN + n;
#pragma unroll 8
    for (int k = 0; k < HN; k++) acc += b2f_[k] * Wf_[(size_t)k * HN];
    out[f * HN + n] = acc;
}

// ---------------------------------------------------------------------------
// k_gate2: M=128, N=128 (grid.y = n-half), 256 thr, 2 CTAs/SM.
// ---------------------------------------------------------------------------
__global__ void __launch_bounds__(256, 2) k_gate2(
    const float* __restrict__ x, const float* __restrict__ w1, const float* __restrict__ b1)
{
    extern __shared__ char sm[];
    const uint32_t smb = smem_u32(sm);
    const int tid = threadIdx.x, lane = tid & 31, wid = tid >> 5;
    const int wm = wid & 3, wn = wid >> 2;
    const int m0 = blockIdx.x * 128;
    const int n0 = blockIdx.y * 128;
    const int f  = blockIdx.z;
    const size_t WS = (size_t)HN * HN;

    float acc[2][8][4];
#pragma unroll
    for (int a = 0; a < 2; a++)
#pragma unroll
        for (int b = 0; b < 8; b++)
#pragma unroll
            for (int c = 0; c < 4; c++) acc[a][b][c] = 0.f;

    const int grow = tid & 127, gseg = tid >> 7;
    const float xv = x[(m0 + grow) * FN + f];
    const float* __restrict__ w1f = w1 + f * HN;
    const float* __restrict__ b1f = b1 + f * HN;
    const __nv_bfloat16* __restrict__ Bh_ = g_cgh + WS * f + n0;
    const __nv_bfloat16* __restrict__ Bl_ = g_cgl + WS * f + n0;
    uint4 rbh[2], rbl[2];

#define G2_LOADB(kt) do { \
    _Pragma("unroll") \
    for (int i = 0; i < 2; i++) { \
        const int u = tid + 256 * i; \
        const int row = u >> 4, cu = u & 15; \
        rbh[i] = *(const uint4*)(Bh_ + (size_t)((kt) * 32 + row) * HN + cu * 8); \
        rbl[i] = *(const uint4*)(Bl_ + (size_t)((kt) * 32 + row) * HN + cu * 8); \
    } } while (0)
#define G2_STAGEB() do { \
    _Pragma("unroll") \
    for (int i = 0; i < 2; i++) { \
        const int u = tid + 256 * i; \
        const int row = u >> 4, cu = u & 15; \
        const uint32_t o = row * BST2 + cu * 16; \
        *(uint4*)(sm + C_BH + o) = rbh[i]; \
        *(uint4*)(sm + C_BL + o) = rbl[i]; \
    } } while (0)
#define G2_GENA(k0) do { \
    _Pragma("unroll") \
    for (int oct = 0; oct < 2; oct++) { \
        const int kk = (k0) + gseg * 16 + oct * 8; \
        float4 wa = *(const float4*)(w1f + kk),  wb = *(const float4*)(w1f + kk + 4); \
        float4 ca = *(const float4*)(b1f + kk),  cb = *(const float4*)(b1f + kk + 4); \
        float v[8] = { eluf(xv*wa.x+ca.x), eluf(xv*wa.y+ca.y), eluf(xv*wa.z+ca.z), eluf(xv*wa.w+ca.w), \
                       eluf(xv*wb.x+cb.x), eluf(xv*wb.y+cb.y), eluf(xv*wb.z+cb.z), eluf(xv*wb.w+cb.w) }; \
        uint4 H = { pack_hi2(v[0],v[1]), pack_hi2(v[2],v[3]), pack_hi2(v[4],v[5]), pack_hi2(v[6],v[7]) }; \
        uint4 L = { pack_lo2(v[0],v[1]), pack_lo2(v[2],v[3]), pack_lo2(v[4],v[5]), pack_lo2(v[6],v[7]) }; \
        const uint32_t o = grow * AST + gseg * 32 + oct * 16; \
        *(uint4*)(sm + o) = H; \
        *(uint4*)(sm + S_AL + o) = L; \
    } } while (0)

    G2_LOADB(0);
    for (int kt = 0; kt < 8; kt++) {
        G2_GENA(kt * 32);
        G2_STAGEB();
        __syncthreads();
        if (kt + 1 < 8) G2_LOADB(kt + 1);
        ktile(smb, smb + S_AL, smb + C_BH, smb + C_BL, BST2, acc, lane, wm, wn);
        __syncthreads();
    }
#undef G2_LOADB
#undef G2_STAGEB
#undef G2_GENA

#pragma unroll
    for (int mt = 0; mt < 2; mt++)
#pragma unroll
        for (int j = 0; j < 8; j++) {
            const int n  = n0 + wn * 64 + j * 8 + (lane & 3) * 2;
            const int r0 = wm * 32 + mt * 16 + (lane >> 2);
            float2 bb = *(const float2*)(g_cbg + f * HN + n);
            float2 o0 = { sigf(acc[mt][j][0] + bb.x), sigf(acc[mt][j][1] + bb.y) };
            float2 o1 = { sigf(acc[mt][j][2] + bb.x), sigf(acc[mt][j][3] + bb.y) };
            *(float2*)(g_sg + ((size_t)f * BTN + m0 + r0) * HN + n) = o0;
            *(float2*)(g_sg + ((size_t)f * BTN + m0 + r0 + 8) * HN + n) = o1;
        }
}

// ---------------------------------------------------------------------------
// k_val: value GEMM + GLU + skip + LN fused (512 thr, M=128/N=256).
// ---------------------------------------------------------------------------
__global__ void __launch_bounds__(512, 1) k_val(
    const float* __restrict__ x, const float* __restrict__ w1, const float* __restrict__ b1,
    const float* __restrict__ ws, const float* __restrict__ bs,
    const float* __restrict__ gamma, const float* __restrict__ beta)
{
    extern __shared__ char sm[];
    const uint32_t smb = smem_u32(sm);
    const int tid = threadIdx.x, lane = tid & 31, wid = tid >> 5;
    const int wm = wid & 3, wn = wid >> 2;
    const int m0 = blockIdx.x * 128, f = blockIdx.y;

    float acc[2][8][4];
#pragma unroll
    for (int a = 0; a < 2; a++)
#pragma unroll
        for (int b = 0; b < 8; b++)
#pragma unroll
            for (int c = 0; c < 4; c++) acc[a][b][c] = 0.f;

    const int grow = tid & 127, gseg = tid >> 7;
    const float xv = x[(m0 + grow) * FN + f];
    const float* __restrict__ w1f = w1 + f * HN;
    const float* __restrict__ b1f = b1 + f * HN;
    const __nv_bfloat16* __restrict__ Bh_ = g_cfh + (size_t)f * HN * HN;
    const __nv_bfloat16* __restrict__ Bl_ = g_cfl + (size_t)f * HN * HN;
    uint4 rbh[2], rbl[2];

#define V_GENA(k0) do { \
    const int kk = (k0) + gseg * 8; \
    float4 wa = *(const float4*)(w1f + kk),  wb = *(const float4*)(w1f + kk + 4); \
    float4 ca = *(const float4*)(b1f + kk),  cb = *(const float4*)(b1f + kk + 4); \
    float v[8] = { eluf(xv*wa.x+ca.x), eluf(xv*wa.y+ca.y), eluf(xv*wa.z+ca.z), eluf(xv*wa.w+ca.w), \
                   eluf(xv*wb.x+cb.x), eluf(xv*wb.y+cb.y), eluf(xv*wb.z+cb.z), eluf(xv*wb.w+cb.w) }; \
    uint4 H = { pack_hi2(v[0],v[1]), pack_hi2(v[2],v[3]), pack_hi2(v[4],v[5]), pack_hi2(v[6],v[7]) }; \
    uint4 L = { pack_lo2(v[0],v[1]), pack_lo2(v[2],v[3]), pack_lo2(v[4],v[5]), pack_lo2(v[6],v[7]) }; \
    const uint32_t o = grow * AST + gseg * 16; \
    *(uint4*)(sm + o) = H; \
    *(uint4*)(sm + S_AL + o) = L; } while (0)
#define V_LOADB(kt) do { \
    _Pragma("unroll") \
    for (int i = 0; i < 2; i++) { \
        const int u = tid + 512 * i; \
        const int row = u >> 5, cu = u & 31; \
        rbh[i] = *(const uint4*)(Bh_ + (size_t)((kt) * 32 + row) * HN + cu * 8); \
        rbl[i] = *(const uint4*)(Bl_ + (size_t)((kt) * 32 + row) * HN + cu * 8); \
    } } while (0)
#define V_STAGEB() do { \
    _Pragma("unroll") \
    for (int i = 0; i < 2; i++) { \
        const int u = tid + 512 * i; \
        const int row = u >> 5, cu = u & 31; \
        const uint32_t o = row * BST + cu * 16; \
        *(uint4*)(sm + S_BH + o) = rbh[i]; \
        *(uint4*)(sm + S_BL + o) = rbl[i]; \
    } } while (0)

    V_LOADB(0);
    for (int kt = 0; kt < 8; kt++) {
        V_GENA(kt * 32);
        V_STAGEB();
        __syncthreads();
        if (kt + 1 < 8) V_LOADB(kt + 1);
        ktile(smb, smb + S_AL, smb + S_BH, smb + S_BL, BST, acc, lane, wm, wn);
        __syncthreads();
    }
#undef V_GENA
#undef V_LOADB
#undef V_STAGEB

    // --- epilogue: GLU + skip into acc (in place) ---
#pragma unroll
    for (int mt = 0; mt < 2; mt++) {
        const int rA = m0 + wm * 32 + mt * 16 + (lane >> 2);
        const float xa = x[rA * FN + f];
        const float xb = x[(rA + 8) * FN + f];
#pragma unroll
        for (int j = 0; j < 8; j++) {
            const int n = wn * 64 + j * 8 + (lane & 3) * 2;
            float2 cb  = *(const float2*)(g_cbf + f * HN + n);
            float2 wsv = *(const float2*)(ws + f * HN + n);
            float2 bsv = *(const float2*)(bs + f * HN + n);
            float2 sg0 = *(const float2*)(g_sg + ((size_t)f * BTN + rA) * HN + n);
            float2 sg1 = *(const float2*)(g_sg + ((size_t)f * BTN + rA + 8) * HN + n);
            acc[mt][j][0] = sg0.x * (acc[mt][j][0] + cb.x) + xa * wsv.x + bsv.x;
            acc[mt][j][1] = sg0.y * (acc[mt][j][1] + cb.y) + xa * wsv.y + bsv.y;
            acc[mt][j][2] = sg1.x * (acc[mt][j][2] + cb.x) + xb * wsv.x + bsv.x;
            acc[mt][j][3] = sg1.y * (acc[mt][j][3] + cb.y) + xb * wsv.y + bsv.y;
        }
    }
    // --- LN partials ---
    float2* part = (float2*)sm;   // [128 rows][4 wn]
#pragma unroll
    for (int mt = 0; mt < 2; mt++) {
        float s0 = 0.f, q0 = 0.f, s1 = 0.f, q1 = 0.f;
#pragma unroll
        for (int j = 0; j < 8; j++) {
            s0 += acc[mt][j][0] + acc[mt][j][1];
            q0 += acc[mt][j][0] * acc[mt][j][0] + acc[mt][j][1] * acc[mt][j][1];
            s1 += acc[mt][j][2] + acc[mt][j][3];
            q1 += acc[mt][j][2] * acc[mt][j][2] + acc[mt][j][3] * acc[mt][j][3];
        }
#pragma unroll
        for (int o = 1; o <= 2; o <<= 1) {
            s0 += __shfl_xor_sync(0xffffffffu, s0, o);
            q0 += __shfl_xor_sync(0xffffffffu, q0, o);
            s1 += __shfl_xor_sync(0xffffffffu, s1, o);
            q1 += __shfl_xor_sync(0xffffffffu, q1, o);
        }
        if ((lane & 3) == 0) {
            const int r0 = wm * 32 + mt * 16 + (lane >> 2);
            part[r0 * 4 + wn]       = make_float2(s0, q0);
            part[(r0 + 8) * 4 + wn] = make_float2(s1, q1);
        }
    }
    __syncthreads();
#pragma unroll
    for (int mt = 0; mt < 2; mt++) {
        const int r0 = wm * 32 + mt * 16 + (lane >> 2);
        float2 p0 = part[r0 * 4 + 0], p1 = part[r0 * 4 + 1];
        float2 p2 = part[r0 * 4 + 2], p3 = part[r0 * 4 + 3];
        float sA = p0.x + p1.x + p2.x + p3.x, qA = p0.y + p1.y + p2.y + p3.y;
        p0 = part[(r0 + 8) * 4 + 0]; p1 = part[(r0 + 8) * 4 + 1];
        p2 = part[(r0 + 8) * 4 + 2]; p3 = part[(r0 + 8) * 4 + 3];
        float sB = p0.x + p1.x + p2.x + p3.x, qB = p0.y + p1.y + p2.y + p3.y;
        const float mA = sA * (1.f / 256.f);
        float vA = qA * (1.f / 256.f) - mA * mA; vA = vA > 0.f ? vA : 0.f;
        const float rA_ = rsqrtf(vA + 1e-5f);
        const float mB = sB * (1.f / 256.f);
        float vB = qB * (1.f / 256.f) - mB * mB; vB = vB > 0.f ? vB : 0.f;
        const float rB_ = rsqrtf(vB + 1e-5f);
        float* o0p = g_stk + (size_t)(m0 + r0) * FHN + f * HN;
        float* o1p = g_stk + (size_t)(m0 + r0 + 8) * FHN + f * HN;
#pragma unroll
        for (int j = 0; j < 8; j++) {
            const int n = wn * 64 + j * 8 + (lane & 3) * 2;
            float2 gm = *(const float2*)(gamma + f * HN + n);
            float2 bt = *(const float2*)(beta + f * HN + n);
            *(float2*)(o0p + n) = make_float2((acc[mt][j][0] - mA) * rA_ * gm.x + bt.x,
                                              (acc[mt][j][1] - mA) * rA_ * gm.y + bt.y);
            *(float2*)(o1p + n) = make_float2((acc[mt][j][2] - mB) * rB_ * gm.x + bt.x,
                                              (acc[mt][j][3] - mB) * rB_ * gm.y + bt.y);
        }
    }
}

// ---------------------------------------------------------------------------
// k_gemmS2: M=128, N=128, 256 thr, 2 CTAs/SM. A fp32 converted at stage time.
// ---------------------------------------------------------------------------
__global__ void __launch_bounds__(256, 2) k_gemmS2(const float* __restrict__ sb1)
{
    extern __shared__ char sm[];
    const uint32_t smb = smem_u32(sm);
    const int tid = threadIdx.x, lane = tid & 31, wid = tid >> 5;
    const int wm = wid & 3, wn = wid >> 2;
    const int m0 = blockIdx.x * 128;
    const int n0 = blockIdx.y * 128;

    float acc[2][8][4];
#pragma unroll
    for (int a = 0; a < 2; a++)
#pragma unroll
        for (int b = 0; b < 8; b++)
#pragma unroll
            for (int c = 0; c < 4; c++) acc[a][b][c] = 0.f;

    const __nv_bfloat16* __restrict__ Bh_ = g_s1h + n0;
    const __nv_bfloat16* __restrict__ Bl_ = g_s1l + n0;
    uint4 rbh[2], rbl[2];

#define S2_LOADB(kt) do { \
    _Pragma("unroll") \
    for (int i = 0; i < 2; i++) { \
        const int u = tid + 256 * i; \
        const int row = u >> 4, cu = u & 15; \
        rbh[i] = *(const uint4*)(Bh_ + (size_t)((kt) * 32 + row) * HN + cu * 8); \
        rbl[i] = *(const uint4*)(Bl_ + (size_t)((kt) * 32 + row) * HN + cu * 8); \
    } } while (0)
#define S2_STAGEB() do { \
    _Pragma("unroll") \
    for (int i = 0; i < 2; i++) { \
        const int u = tid + 256 * i; \
        const int row = u >> 4, cu = u & 15; \
        const uint32_t o = row * BST2 + cu * 16; \
        *(uint4*)(sm + C_BH + o) = rbh[i]; \
        *(uint4*)(sm + C_BL + o) = rbl[i]; \
    } } while (0)
#define S2_STAGEA(kt) do { \
    _Pragma("unroll") \
    for (int i = 0; i < 4; i++) { \
        const int u = tid + 256 * i; \
        const int row = u >> 3, cu = u & 7; \
        float4 v = *(const float4*)(g_stk + (size_t)(m0 + row) * FHN + (kt) * 32 + cu * 4); \
        const uint32_t o = row * AST + cu * 8; \
        *(uint2*)(sm + o)        = make_uint2(pack_hi2(v.x, v.y), pack_hi2(v.z, v.w)); \
        *(uint2*)(sm + S_AL + o) = make_uint2(pack_lo2(v.x, v.y), pack_lo2(v.z, v.w)); \
    } } while (0)

    S2_LOADB(0);
    const int C = FHN / 32;
    for (int kt = 0; kt < C; kt++) {
        S2_STAGEA(kt);
        S2_STAGEB();
        __syncthreads();
        if (kt + 1 < C) S2_LOADB(kt + 1);
        ktile(smb, smb + S_AL, smb + C_BH, smb + C_BL, BST2, acc, lane, wm, wn);
        __syncthreads();
    }
#undef S2_LOADB
#undef S2_STAGEB
#undef S2_STAGEA

#pragma unroll
    for (int mt = 0; mt < 2; mt++)
#pragma unroll
        for (int j = 0; j < 8; j++) {
            const int n  = n0 + wn * 64 + j * 8 + (lane & 3) * 2;
            const int r0 = wm * 32 + mt * 16 + (lane >> 2);
            float2 bb = *(const float2*)(sb1 + n);
            float2 o0 = { eluf(acc[mt][j][0] + bb.x), eluf(acc[mt][j][1] + bb.y) };
            float2 o1 = { eluf(acc[mt][j][2] + bb.x), eluf(acc[mt][j][3] + bb.y) };
            *(float2*)(g_sh + (size_t)(m0 + r0) * HN + n) = o0;
            *(float2*)(g_sh + (size_t)(m0 + r0 + 8) * HN + n) = o1;
        }
}

// ---------------------------------------------------------------------------
// k_selt: fused sres + selection tail. One warp per token.
// ---------------------------------------------------------------------------
__global__ __launch_bounds__(256) void k_selt(
    const float* __restrict__ ssw, const float* __restrict__ ssb,
    const float* __restrict__ sw2, const float* __restrict__ sb2,
    const float* __restrict__ swg, const float* __restrict__ sbg,
    const float* __restrict__ swf, const float* __restrict__ sbf,
    const float* __restrict__ sgm, const float* __restrict__ sbt)
{
    const int lane = threadIdx.x & 31;
    const int m    = blockIdx.x * 8 + (threadIdx.x >> 5);
    const float* __restrict__ a = g_stk + (size_t)m * FHN;
    float sres = 0.f;
#pragma unroll 4
    for (int k = 0; k < FHN; k += 4) {
        float4 av = *(const float4*)(a + k);
        sres += av.x * ssw[(k + 0) * FN + lane];
        sres += av.y * ssw[(k + 1) * FN + lane];
        sres += av.z * ssw[(k + 2) * FN + lane];
        sres += av.w * ssw[(k + 3) * FN + lane];
    }
    sres += ssb[lane];
    const float* __restrict__ sh = g_sh + (size_t)m * HN;
    float shv[8];
#pragma unroll
    for (int i = 0; i < 8; i++) shv[i] = sh[i * 32 + lane];
    float acc = sb2[lane];
#pragma unroll 8
    for (int h = 0; h < HN; h++) {
        float s = __shfl_sync(0xffffffffu, shv[h >> 5], h & 31);
        acc += s * sw2[h * FN + lane];
    }
    float ag = sbg[lane], af = sbf[lane];
#pragma unroll
    for (int i = 0; i < FN; i++) {
        float s = __shfl_sync(0xffffffffu, acc, i);
        ag += s * swg[i * FN + lane];
        af += s * swf[i * FN + lane];
    }
    const float pre = sres + sigf(ag) * af;
    float s1 = pre;
#pragma unroll
    for (int o = 16; o > 0; o >>= 1) s1 += __shfl_xor_sync(0xffffffffu, s1, o);
    const float mean = s1 * (1.f / 32.f);
    const float d = pre - mean;
    float q = d * d;
#pragma unroll
    for (int o = 16; o > 0; o >>= 1) q += __shfl_xor_sync(0xffffffffu, q, o);
    const float y = d * rsqrtf(q * (1.f / 32.f) + 1e-5f) * sgm[lane] + sbt[lane];
    float mx = y;
#pragma unroll
    for (int o = 16; o > 0; o >>= 1) mx = fmaxf(mx, __shfl_xor_sync(0xffffffffu, mx, o));
    const float e = __expf(y - mx);
    float se = e;
#pragma unroll
    for (int o = 16; o > 0; o >>= 1) se += __shfl_xor_sync(0xffffffffu, se, o);
    g_wts[m * FN + lane] = e / se;
}

// ---------------------------------------------------------------------------
__global__ __launch_bounds__(256) void k_out(float* __restrict__ out)
{
    const int m = blockIdx.x * 4 + (threadIdx.x >> 6);
    const int c = threadIdx.x & 63;
    const float4* __restrict__ sp = (const float4*)(g_stk + (size_t)m * FHN);
    const float* __restrict__ wp = g_wts + m * FN;
    float4 acc = make_float4(0.f, 0.f, 0.f, 0.f);
#pragma unroll
    for (int f = 0; f < FN; f++) {
        const float w = wp[f];
        float4 v = sp[f * 64 + c];
        acc.x += w * v.x; acc.y += w * v.y; acc.z += w * v.z; acc.w += w * v.w;
    }
    ((float4*)out)[(size_t)m * 64 + c] = acc;
}

// ---------------------------------------------------------------------------
extern "C" void kernel_launch(void* const* d_in, const int* in_sizes, int n_in,
                              void* d_out, int out_size)
{
    const float* x    = (const float*)d_in[0];
    const float* w1   = (const float*)d_in[1];
    const float* b1   = (const float*)d_in[2];
    const float* w2   = (const float*)d_in[3];
    const float* b2   = (const float*)d_in[4];
    const float* wg   = (const float*)d_in[5];
    const float* bg   = (const float*)d_in[6];
    const float* wf   = (const float*)d_in[7];
    const float* bf   = (const float*)d_in[8];
    const float* gamma= (const float*)d_in[9];
    const float* beta = (const float*)d_in[10];
    const float* ws   = (const float*)d_in[11];
    const float* bs   = (const float*)d_in[12];
    const float* sw1  = (const float*)d_in[13];
    const float* sb1  = (const float*)d_in[14];
    const float* sw2  = (const float*)d_in[15];
    const float* sb2  = (const float*)d_in[16];
    const float* swg  = (const float*)d_in[17];
    const float* sbg  = (const float*)d_in[18];
    const float* swf  = (const float*)d_in[19];
    const float* sbf  = (const float*)d_in[20];
    const float* sgm  = (const float*)d_in[21];
    const float* sbt  = (const float*)d_in[22];
    const float* ssw  = (const float*)d_in[23];
    const float* ssb  = (const float*)d_in[24];
    float* out = (float*)d_out;

    cudaFuncSetAttribute(k_wsplit, cudaFuncAttributeMaxDynamicSharedMemorySize, SM_1B);
    cudaFuncSetAttribute(k_gate2,  cudaFuncAttributeMaxDynamicSharedMemorySize, SM_2C);
    cudaFuncSetAttribute(k_val,    cudaFuncAttributeMaxDynamicSharedMemorySize, SM_1B);
    cudaFuncSetAttribute(k_gemmS2, cudaFuncAttributeMaxDynamicSharedMemorySize, SM_2C);

    __nv_bfloat16 *cgh, *cgl, *cfh, *cfl, *s1h, *s1l;
    cudaGetSymbolAddress((void**)&cgh, g_cgh);
    cudaGetSymbolAddress((void**)&cgl, g_cgl);
    cudaGetSymbolAddress((void**)&cfh, g_cfh);
    cudaGetSymbolAddress((void**)&cfl, g_cfl);
    cudaGetSymbolAddress((void**)&s1h, g_s1h);
    cudaGetSymbolAddress((void**)&s1l, g_s1l);

    k_wsplit<<<dim3(2, FN), 512, SM_1B>>>(w2, wg, cgh, cgl);
    k_wsplit<<<dim3(2, FN), 512, SM_1B>>>(w2, wf, cfh, cfl);
    k_bias  <<<dim3(FN, 2), 256>>>(b2, wg, wf, bg, bf);
    k_split <<<(FHN * HN) / 1024, 256>>>(sw1, s1h, s1l);

    k_gate2<<<dim3(BTN / 128, 2, FN), 256, SM_2C>>>(x, w1, b1);
    k_val  <<<dim3(BTN / 128, FN), 512, SM_1B>>>(x, w1, b1, ws, bs, gamma, beta);

    k_gemmS2<<<dim3(BTN / 128, 2), 256, SM_2C>>>(sb1);
    k_selt <<<BTN / 8, 256>>>(ssw, ssb, sw2, sb2, swg, sbg, swf, sbf, sgm, sbt);
    k_out  <<<BTN / 4, 256>>>(out);
}